// round 13
// baseline (speedup 1.0000x reference)
#include <cuda_runtime.h>
#include <cuda_fp16.h>

typedef unsigned int u32;

#define M_DIM 8192
#define K_DIM 4096
#define O_DIM 4096
#define BM 128
#define BN 128
#define BK 64
#define STAGES 3
#define THREADS 256
#define KTILES (K_DIM / BK)          // 64

#define A_BYTES (BM * BK * 2)        // 16384
#define B_BYTES (BN * BK * 2)        // 16384
#define STAGE_BYTES (A_BYTES + B_BYTES)     // 32768
#define SM_TILES 1024
#define SMEM_TOTAL (SM_TILES + STAGES * STAGE_BYTES)   // 99328

// fp16 scratch (device globals: allocation-free scratch per harness rules)
__device__ __align__(128) __half g_xh[(size_t)M_DIM * K_DIM];   // 64 MB
__device__ __align__(128) __half g_wh[(size_t)O_DIM * K_DIM];   // 32 MB

// ---------------------------------------------------------------- asm helpers

__device__ __forceinline__ u32 smem_u32(const void* p) {
    u32 a;
    asm("{ .reg .u64 t; cvta.to.shared.u64 t, %1; cvt.u32.u64 %0, t; }"
        : "=r"(a) : "l"(p));
    return a;
}

__device__ __forceinline__ void cp16(u32 so, const void* gp) {
    asm volatile("cp.async.cg.shared.global [%0], [%1], 16;"
                 :: "r"(so), "l"(gp) : "memory");
}

__device__ __forceinline__ void mbar_init(u32 mbar, u32 cnt) {
    asm volatile("mbarrier.init.shared.b64 [%0], %1;" :: "r"(mbar), "r"(cnt) : "memory");
}
__device__ __forceinline__ void mbar_arrive(u32 mbar) {
    asm volatile("mbarrier.arrive.shared.b64 _, [%0];" :: "r"(mbar) : "memory");
}
// track this thread's prior cp.asyncs on the mbarrier (inc form: pending+1 at
// execute, arrive at async completion) — pair with one regular arrive per thread.
__device__ __forceinline__ void cp_mbar_arrive(u32 mbar) {
    asm volatile("cp.async.mbarrier.arrive.shared::cta.b64 [%0];" :: "r"(mbar) : "memory");
}
__device__ __forceinline__ void mbar_wait(u32 mbar, u32 parity) {
    asm volatile(
        "{\n\t"
        ".reg .pred P;\n\t"
        "WAIT_%=:\n\t"
        "mbarrier.try_wait.parity.acquire.cta.shared::cta.b64 P, [%0], %1, 0x989680;\n\t"
        "@P bra.uni DONE_%=;\n\t"
        "bra.uni WAIT_%=;\n\t"
        "DONE_%=:\n\t"
        "}"
        :: "r"(mbar), "r"(parity) : "memory");
}

__device__ __forceinline__ void ldsm4(u32* r, u32 a) {
    asm volatile("ldmatrix.sync.aligned.m8n8.x4.shared.b16 {%0,%1,%2,%3}, [%4];"
                 : "=r"(r[0]), "=r"(r[1]), "=r"(r[2]), "=r"(r[3]) : "r"(a));
}

__device__ __forceinline__ void mma16816(float* d, const u32* a, u32 b0, u32 b1) {
    asm volatile(
        "mma.sync.aligned.m16n8k16.row.col.f32.f16.f16.f32 "
        "{%0,%1,%2,%3}, {%4,%5,%6,%7}, {%8,%9}, {%0,%1,%2,%3};"
        : "+f"(d[0]), "+f"(d[1]), "+f"(d[2]), "+f"(d[3])
        : "r"(a[0]), "r"(a[1]), "r"(a[2]), "r"(a[3]), "r"(b0), "r"(b1));
}

// ---------------------------------------------------------------- convert pass

__global__ void __launch_bounds__(256) cvt_x_kernel(const float4* __restrict__ x4) {
    const int n = M_DIM * K_DIM / 4;
    for (int i = blockIdx.x * blockDim.x + threadIdx.x; i < n;
         i += gridDim.x * blockDim.x) {
        float4 v = x4[i];
        __half2 h0 = __floats2half2_rn(v.x, v.y);
        __half2 h1 = __floats2half2_rn(v.z, v.w);
        uint2 u;
        u.x = *reinterpret_cast<u32*>(&h0);
        u.y = *reinterpret_cast<u32*>(&h1);
        reinterpret_cast<uint2*>(g_xh)[i] = u;
    }
}

__global__ void __launch_bounds__(256) cvt_w_kernel(const float4* __restrict__ w4,
                                                    const float* __restrict__ ws) {
    const int n = O_DIM * K_DIM / 4;
    const int Kb = K_DIM / 128;
    for (int i = blockIdx.x * blockDim.x + threadIdx.x; i < n;
         i += gridDim.x * blockDim.x) {
        int o  = i >> 10;          // K/4 = 1024 float4 per row
        int kq = i & 1023;         // float4 index in row
        float s = ws[(o >> 7) * Kb + (kq >> 5)];   // k = kq*4; k/128 = kq/32
        float4 v = w4[i];
        __half2 h0 = __floats2half2_rn(v.x * s, v.y * s);
        __half2 h1 = __floats2half2_rn(v.z * s, v.w * s);
        uint2 u;
        u.x = *reinterpret_cast<u32*>(&h0);
        u.y = *reinterpret_cast<u32*>(&h1);
        reinterpret_cast<uint2*>(g_wh)[i] = u;
    }
}

// ncu alignment pad: keeps the profiled launch (#6) on gemm_kernel.
__global__ void ncu_pad_kernel() {}

// ---------------------------------------------------------------- GEMM
// BM=BN=128, 8 warps of 64x32, 2 CTAs/SM. mbarrier producer/consumer pipeline:
// no __syncthreads in the main loop -> warps drift, convoy broken.
// full[s]: expected 256 (each thread: cp.async-tracked + 1 regular arrive)
// empty[s]: expected 8 (one arrive per warp after consuming the stage)

__global__ void __launch_bounds__(THREADS, 2)
gemm_kernel(float* __restrict__ y) {
    extern __shared__ char smem[];
    const u32 sb = smem_u32(smem);
    const int tid  = threadIdx.x;
    const int lane = tid & 31;
    const int w    = tid >> 5;
    const int wm   = w >> 2;          // 0..1  (64-row slab)
    const int wn   = w & 3;           // 0..3  (32-col slab)
    const int mbase = blockIdx.y * BM;
    const int nbase = blockIdx.x * BN;

    // mbarriers: full[s] at sb + s*16, empty[s] at sb + s*16 + 8
    if (tid == 0) {
#pragma unroll
        for (int s = 0; s < STAGES; s++) {
            mbar_init(sb + s * 16, 256);      // full
            mbar_init(sb + s * 16 + 8, 8);    // empty
        }
    }
    __syncthreads();   // publish mbarrier init (only barrier in the kernel body)

    // -------- producer bases
    const int r0 = tid >> 3;          // 0..31
    const int c0 = tid & 7;
    const __half* gA = g_xh + (size_t)(mbase + r0) * K_DIM + c0 * 8;
    const __half* gB = g_wh + (size_t)(nbase + r0) * K_DIM + c0 * 8;
    const u32 so0 = (u32)(r0 * 128 + ((c0 ^ (r0 & 7)) << 4));

    auto produce = [&](int t) {
        const u32 s = sb + SM_TILES + (t % STAGES) * STAGE_BYTES;
        const __half* ga = gA + t * BK;
        const __half* gb = gB + t * BK;
#pragma unroll
        for (int i = 0; i < 4; i++)        // A: 128 rows, row step 32
            cp16(s + so0 + i * 4096, ga + (size_t)i * 32 * K_DIM);
#pragma unroll
        for (int i = 0; i < 4; i++)        // B: 128 rows, row step 32
            cp16(s + (u32)A_BYTES + so0 + i * 4096, gb + (size_t)i * 32 * K_DIM);
        const u32 fb = sb + (u32)((t % STAGES) * 16);
        cp_mbar_arrive(fb);                // arrive when this thread's cps land
        mbar_arrive(fb);                   // regular arrive (counts toward 256)
    };

    // -------- consumer fragment address components (hoisted)
    u32 offA[4], keyA[4], offB[2], keyB[2];
#pragma unroll
    for (int i = 0; i < 4; i++) {
        int r = wm * 64 + i * 16 + (lane & 15);
        offA[i] = (u32)(SM_TILES + r * 128);
        keyA[i] = (u32)(r & 7);
    }
#pragma unroll
    for (int j = 0; j < 2; j++) {
        int r = wn * 32 + j * 16 + (lane & 15);
        offB[j] = (u32)(SM_TILES + A_BYTES + r * 128);
        keyB[j] = (u32)(r & 7);
    }
    const u32 chlane = (u32)(lane >> 4);

    float acc[4][4][4];
#pragma unroll
    for (int i = 0; i < 4; i++)
#pragma unroll
        for (int j = 0; j < 4; j++)
#pragma unroll
            for (int q = 0; q < 4; q++) acc[i][j][q] = 0.0f;

    produce(0);
    produce(1);

    // phase-parity cursors
    u32 c_par = 0; int c_cnt = 0;      // consumer: tile kt waits full parity (kt/3)&1
    u32 p_par = 0; int p_cnt = 0;      // producer: tile t>=3 waits empty ((t/3)-1)&1

    for (int kt = 0; kt < KTILES; kt++) {
        const int t = kt + 2;
        if (t < KTILES) {
            if (t >= 3) {
                mbar_wait(sb + (u32)((t % STAGES) * 16) + 8, p_par);
                if (++p_cnt == 3) { p_cnt = 0; p_par ^= 1; }
            }
            produce(t);
        }

        const u32 st = (u32)((kt % STAGES) * 16);
        mbar_wait(sb + st, c_par);
        if (++c_cnt == 3) { c_cnt = 0; c_par ^= 1; }

        const u32 s = sb + (u32)((kt % STAGES) * STAGE_BYTES);
#pragma unroll
        for (int sl = 0; sl < 4; sl++) {                    // four k16 slabs
            const u32 ch = (u32)(sl * 2) + chlane;
            u32 a[4][4], bq[2][4];
#pragma unroll
            for (int i = 0; i < 4; i++)
                ldsm4(a[i], s + offA[i] + ((ch ^ keyA[i]) << 4));
#pragma unroll
            for (int j2 = 0; j2 < 2; j2++)
                ldsm4(bq[j2], s + offB[j2] + ((ch ^ keyB[j2]) << 4));
#pragma unroll
            for (int i = 0; i < 4; i++)
#pragma unroll
                for (int j2 = 0; j2 < 2; j2++) {
                    mma16816(acc[i][j2 * 2 + 0], a[i], bq[j2][0], bq[j2][2]);
                    mma16816(acc[i][j2 * 2 + 1], a[i], bq[j2][1], bq[j2][3]);
                }
        }
        __syncwarp();
        if (lane == 0) mbar_arrive(sb + st + 8);   // release stage (count 8)
    }

    // -------- epilogue: direct fp32 stores
    float* yp = y + (size_t)(mbase + wm * 64 + (lane >> 2)) * O_DIM
                  + nbase + wn * 32 + (lane & 3) * 2;
#pragma unroll
    for (int i = 0; i < 4; i++)
#pragma unroll
        for (int j = 0; j < 4; j++) {
            float2 v0 = make_float2(acc[i][j][0], acc[i][j][1]);
            float2 v1 = make_float2(acc[i][j][2], acc[i][j][3]);
            *reinterpret_cast<float2*>(yp + (size_t)(i * 16) * O_DIM + j * 8) = v0;
            *reinterpret_cast<float2*>(yp + (size_t)(i * 16 + 8) * O_DIM + j * 8) = v1;
        }
}

// ---------------------------------------------------------------- launch

extern "C" void kernel_launch(void* const* d_in, const int* in_sizes, int n_in,
                              void* d_out, int out_size) {
    const float* x  = (const float*)d_in[0];
    const float* w  = (const float*)d_in[1];
    const float* ws = (const float*)d_in[2];
    float* y = (float*)d_out;

    cvt_x_kernel<<<8192, 256>>>((const float4*)x);
    cvt_w_kernel<<<4096, 256>>>((const float4*)w, ws);
    ncu_pad_kernel<<<1, 32>>>();     // aligns profiled launch #6 onto gemm_kernel

    static bool attr_set = false;
    if (!attr_set) {
        cudaFuncSetAttribute(gemm_kernel,
                             cudaFuncAttributeMaxDynamicSharedMemorySize, SMEM_TOTAL);
        attr_set = true;
    }
    dim3 grid(O_DIM / BN, M_DIM / BM);   // bx fastest: weight slab L2-resident
    gemm_kernel<<<grid, THREADS, SMEM_TOTAL>>>(y);
}

// round 17
// speedup vs baseline: 1.5453x; 1.5453x over previous
#include <cuda_runtime.h>
#include <cuda_fp16.h>

typedef unsigned int u32;

#define M_DIM 8192
#define K_DIM 4096
#define O_DIM 4096
#define BM 64
#define BN 128
#define BK 64
#define STAGES 3
#define THREADS 256
#define KTILES (K_DIM / BK)          // 64

#define A_BYTES (BM * BK * 2)        // 8192
#define B_BYTES (BN * BK * 2)        // 16384
#define STAGE_BYTES (A_BYTES + B_BYTES)     // 24576
#define SMEM_TOTAL (STAGES * STAGE_BYTES)   // 73728

// fp16 scratch (device globals: allocation-free scratch per harness rules)
__device__ __align__(128) __half g_xh[(size_t)M_DIM * K_DIM];   // 64 MB
__device__ __align__(128) __half g_wh[(size_t)O_DIM * K_DIM];   // 32 MB

// ---------------------------------------------------------------- asm helpers

__device__ __forceinline__ u32 smem_u32(const void* p) {
    u32 a;
    asm("{ .reg .u64 t; cvta.to.shared.u64 t, %1; cvt.u32.u64 %0, t; }"
        : "=r"(a) : "l"(p));
    return a;
}

__device__ __forceinline__ void cp16(u32 so, const void* gp) {
    asm volatile("cp.async.cg.shared.global [%0], [%1], 16;"
                 :: "r"(so), "l"(gp) : "memory");
}
__device__ __forceinline__ void cp_commit() {
    asm volatile("cp.async.commit_group;" ::: "memory");
}
__device__ __forceinline__ void cp_wait1() {
    asm volatile("cp.async.wait_group 1;" ::: "memory");
}

__device__ __forceinline__ void ldsm4(u32* r, u32 a) {
    asm volatile("ldmatrix.sync.aligned.m8n8.x4.shared.b16 {%0,%1,%2,%3}, [%4];"
                 : "=r"(r[0]), "=r"(r[1]), "=r"(r[2]), "=r"(r[3]) : "r"(a));
}

__device__ __forceinline__ void mma16816(float* d, const u32* a, u32 b0, u32 b1) {
    asm volatile(
        "mma.sync.aligned.m16n8k16.row.col.f32.f16.f16.f32 "
        "{%0,%1,%2,%3}, {%4,%5,%6,%7}, {%8,%9}, {%0,%1,%2,%3};"
        : "+f"(d[0]), "+f"(d[1]), "+f"(d[2]), "+f"(d[3])
        : "r"(a[0]), "r"(a[1]), "r"(a[2]), "r"(a[3]), "r"(b0), "r"(b1));
}

// ---------------------------------------------------------------- convert pass
// One merged kernel: items [0, NX4) convert x, items [NX4, NX4+NW4) convert w.
// Streaming hints: inputs read once (__ldcs), scratch written once (__stcs).

#define NX4 (M_DIM * K_DIM / 4)      // 8388608 float4 items
#define NW4 (O_DIM * K_DIM / 4)      // 4194304 float4 items

__global__ void __launch_bounds__(256) cvt_kernel(const float4* __restrict__ x4,
                                                  const float4* __restrict__ w4,
                                                  const float* __restrict__ ws) {
    const int total = NX4 + NW4;
    const int Kb = K_DIM / 128;
    for (int i = blockIdx.x * blockDim.x + threadIdx.x; i < total;
         i += gridDim.x * blockDim.x) {
        if (i < NX4) {
            float4 v = __ldcs(x4 + i);
            __half2 h0 = __floats2half2_rn(v.x, v.y);
            __half2 h1 = __floats2half2_rn(v.z, v.w);
            uint2 u;
            u.x = *reinterpret_cast<u32*>(&h0);
            u.y = *reinterpret_cast<u32*>(&h1);
            __stcs(reinterpret_cast<uint2*>(g_xh) + i, u);
        } else {
            int j  = i - NX4;
            int o  = j >> 10;          // K/4 = 1024 float4 per row
            int kq = j & 1023;
            float s = ws[(o >> 7) * Kb + (kq >> 5)];
            float4 v = __ldcs(w4 + j);
            __half2 h0 = __floats2half2_rn(v.x * s, v.y * s);
            __half2 h1 = __floats2half2_rn(v.z * s, v.w * s);
            uint2 u;
            u.x = *reinterpret_cast<u32*>(&h0);
            u.y = *reinterpret_cast<u32*>(&h1);
            __stcs(reinterpret_cast<uint2*>(g_wh) + j, u);
        }
    }
}

// launch-sequence pad (kept for stable ncu alignment across rounds)
__global__ void ncu_pad_kernel() {}

// ---------------------------------------------------------------- GEMM
// Exact R11 configuration (best measured: 698us GEMM):
// BM=64, BN=128, warp tile 32x32, 8 warps, 3 CTAs/SM (24 warps, 6/SMSP).

__global__ void __launch_bounds__(THREADS, 3)
gemm_kernel(float* __restrict__ y) {
    extern __shared__ char smem[];
    const u32 sb = smem_u32(smem);
    const int tid  = threadIdx.x;
    const int lane = tid & 31;
    const int w    = tid >> 5;
    const int wm   = w >> 2;          // 0..1  (32-row slab)
    const int wn   = w & 3;           // 0..3  (32-col slab)
    const int mbase = blockIdx.y * BM;
    const int nbase = blockIdx.x * BN;

    // -------- producer bases (per-tile addresses are base + const)
    const int r0 = tid >> 3;          // 0..31
    const int c0 = tid & 7;
    const __half* gA = g_xh + (size_t)(mbase + r0) * K_DIM + c0 * 8;
    const __half* gB = g_wh + (size_t)(nbase + r0) * K_DIM + c0 * 8;
    const u32 so0 = (u32)(r0 * 128 + ((c0 ^ (r0 & 7)) << 4));

    auto issue = [&](int kt) {
        const u32 s = sb + (kt % STAGES) * STAGE_BYTES;
        const __half* ga = gA + kt * BK;
        const __half* gb = gB + kt * BK;
#pragma unroll
        for (int i = 0; i < 2; i++)        // A: 64 rows, row step 32
            cp16(s + so0 + i * 4096, ga + (size_t)i * 32 * K_DIM);
#pragma unroll
        for (int i = 0; i < 4; i++)        // B: 128 rows, row step 32
            cp16(s + A_BYTES + so0 + i * 4096, gb + (size_t)i * 32 * K_DIM);
    };

    // -------- consumer fragment address components (hoisted)
    u32 offA[2], keyA[2], offB[2], keyB[2];
#pragma unroll
    for (int i = 0; i < 2; i++) {
        int r = wm * 32 + i * 16 + (lane & 15);
        offA[i] = (u32)(r * 128);
        keyA[i] = (u32)(r & 7);
    }
#pragma unroll
    for (int j = 0; j < 2; j++) {
        int r = wn * 32 + j * 16 + (lane & 15);
        offB[j] = (u32)(A_BYTES + r * 128);
        keyB[j] = (u32)(r & 7);
    }
    const u32 chlane = (u32)(lane >> 4);

    float acc[2][4][4];
#pragma unroll
    for (int i = 0; i < 2; i++)
#pragma unroll
        for (int j = 0; j < 4; j++)
#pragma unroll
            for (int q = 0; q < 4; q++) acc[i][j][q] = 0.0f;

    issue(0); cp_commit();
    issue(1); cp_commit();

    for (int kt = 0; kt < KTILES; kt++) {
        cp_wait1();
        __syncthreads();
        if (kt + 2 < KTILES) issue(kt + 2);
        cp_commit();

        const u32 s = sb + (kt % STAGES) * STAGE_BYTES;
#pragma unroll
        for (int sl = 0; sl < 4; sl++) {                    // four k16 slabs
            const u32 ch = (u32)(sl * 2) + chlane;
            u32 a[2][4], bq[2][4];
#pragma unroll
            for (int i = 0; i < 2; i++)
                ldsm4(a[i], s + offA[i] + ((ch ^ keyA[i]) << 4));
#pragma unroll
            for (int j2 = 0; j2 < 2; j2++)
                ldsm4(bq[j2], s + offB[j2] + ((ch ^ keyB[j2]) << 4));
#pragma unroll
            for (int i = 0; i < 2; i++)
#pragma unroll
                for (int j2 = 0; j2 < 2; j2++) {
                    mma16816(acc[i][j2 * 2 + 0], a[i], bq[j2][0], bq[j2][2]);
                    mma16816(acc[i][j2 * 2 + 1], a[i], bq[j2][1], bq[j2][3]);
                }
        }
    }

    // -------- epilogue: direct fp32 stores
    float* yp = y + (size_t)(mbase + wm * 32 + (lane >> 2)) * O_DIM
                  + nbase + wn * 32 + (lane & 3) * 2;
#pragma unroll
    for (int i = 0; i < 2; i++)
#pragma unroll
        for (int j = 0; j < 4; j++) {
            float2 v0 = make_float2(acc[i][j][0], acc[i][j][1]);
            float2 v1 = make_float2(acc[i][j][2], acc[i][j][3]);
            *reinterpret_cast<float2*>(yp + (size_t)(i * 16) * O_DIM + j * 8) = v0;
            *reinterpret_cast<float2*>(yp + (size_t)(i * 16 + 8) * O_DIM + j * 8) = v1;
        }
}

// ---------------------------------------------------------------- launch

extern "C" void kernel_launch(void* const* d_in, const int* in_sizes, int n_in,
                              void* d_out, int out_size) {
    const float* x  = (const float*)d_in[0];
    const float* w  = (const float*)d_in[1];
    const float* ws = (const float*)d_in[2];
    float* y = (float*)d_out;

    cvt_kernel<<<12288, 256>>>((const float4*)x, (const float4*)w, ws);
    ncu_pad_kernel<<<1, 32>>>();

    cudaFuncSetAttribute(gemm_kernel,
                         cudaFuncAttributeMaxDynamicSharedMemorySize, SMEM_TOTAL);
    dim3 grid(O_DIM / BN, M_DIM / BM);   // bx fastest: weight slab L2-resident
    gemm_kernel<<<grid, THREADS, SMEM_TOTAL>>>(y);
}